// round 5
// baseline (speedup 1.0000x reference)
#include <cuda_runtime.h>

#define BB   128
#define VV   256
#define FF   64
#define NS   4
#define NLR  64
#define NSLR 68
#define KNB  40
#define NOUT 128

// ---------------- scratch ----------------------------------------------------
__device__ float g_mx  [BB * FF];
__device__ float g_s   [BB * VV * NS];
__device__ float g_lr  [BB * VV * NLR];
__device__ float g_mean[BB * VV * NLR];
__device__ float g_max [BB * VV * NLR];
__device__ int   g_nidx[BB * VV * KNB];
__device__ float g_nw  [BB * VV * KNB];

// ---------------- packed f32x2 helpers ---------------------------------------
typedef unsigned long long ull;
__device__ __forceinline__ ull pack2(float lo, float hi) {
    ull r; asm("mov.b64 %0, {%1, %2};" : "=l"(r) : "f"(lo), "f"(hi)); return r;
}
__device__ __forceinline__ void unpack2(ull v, float& lo, float& hi) {
    asm("mov.b64 {%0, %1}, %2;" : "=f"(lo), "=f"(hi) : "l"(v));
}
__device__ __forceinline__ void fma2(ull& d, ull a, ull b) {
    asm("fma.rn.f32x2 %0, %1, %2, %0;" : "+l"(d) : "l"(a), "l"(b));
}

// ============ K_FRONT: per-batch mean + slr = relu(x_cat @ W_slr + b) ========
#define XSP 65
#define KF_SMEM ((VV * XSP + 128 * NSLR + 64 + 256 + NSLR) * 4)
__global__ void k_front(const float* __restrict__ x,
                        const float* __restrict__ W,
                        const float* __restrict__ bias) {
    extern __shared__ float sh[];
    float* xs   = sh;                       // [256][65]
    float* Wsh  = xs + VV * XSP;            // [128][68]
    float* mean = Wsh + 128 * NSLR;         // [64]
    float* red  = mean + 64;                // [256]
    float* cc   = red + 256;                // [68]
    int b = blockIdx.x;
    int t = threadIdx.x;

    const float* xb = x + (size_t)b * VV * FF;
    for (int e = t; e < VV * FF; e += 256) {
        int row = e >> 6, c = e & 63;
        xs[row * XSP + c] = xb[e];
    }
    for (int e = t; e < 128 * NSLR; e += 256) Wsh[e] = W[e];
    __syncthreads();

    {
        int f = t & 63, vg = t >> 6;
        float acc = 0.f;
        #pragma unroll 8
        for (int v = vg * 64; v < vg * 64 + 64; v++) acc += xs[v * XSP + f];
        red[vg * 64 + f] = acc;
    }
    __syncthreads();
    if (t < 64) {
        float m = (red[t] + red[64 + t] + red[128 + t] + red[192 + t]) * (1.0f / VV);
        mean[t] = m;
        g_mx[b * FF + t] = m;
    }
    __syncthreads();

    if (t < NSLR) {
        float acc = bias[t];
        #pragma unroll 8
        for (int k = 0; k < 64; k++) acc += mean[k] * Wsh[(64 + k) * NSLR + t];
        cc[t] = acc;
    }
    __syncthreads();

    int rg = t >> 2;
    int cg = t & 3;
    float acc[4][17];
    #pragma unroll
    for (int u = 0; u < 17; u++) {
        float c0 = cc[cg * 17 + u];
        #pragma unroll
        for (int q = 0; q < 4; q++) acc[q][u] = c0;
    }
    const float* xr = xs + (rg * 4) * XSP;
    #pragma unroll 2
    for (int k = 0; k < 64; k++) {
        float a0 = xr[k], a1 = xr[XSP + k], a2 = xr[2 * XSP + k], a3 = xr[3 * XSP + k];
        const float* wrow = Wsh + k * NSLR + cg * 17;
        #pragma unroll
        for (int u = 0; u < 17; u++) {
            float w = wrow[u];
            acc[0][u] += a0 * w; acc[1][u] += a1 * w;
            acc[2][u] += a2 * w; acc[3][u] += a3 * w;
        }
    }
    #pragma unroll
    for (int q = 0; q < 4; q++) {
        int bv = b * VV + rg * 4 + q;
        #pragma unroll
        for (int u = 0; u < 17; u++) {
            int col = cg * 17 + u;
            float v = fmaxf(acc[q][u], 0.f);
            if (col < NS) g_s [bv * NS  + col]       = v;
            else          g_lr[bv * NLR + col - NS]  = v;
        }
    }
}

// ============ K_SEL: warp-per-row top-40 by (d2, idx) ========================
__global__ void k_sel() {
    __shared__ float4 s_sh[VV];
    int b = blockIdx.x >> 5;
    int i = ((blockIdx.x & 31) << 3) + (threadIdx.x >> 5);
    int l = threadIdx.x & 31;
    if (threadIdx.x < VV)
        s_sh[threadIdx.x] = ((const float4*)g_s)[b * VV + threadIdx.x];
    __syncthreads();

    float4 sv = s_sh[i];
    float d2[8]; unsigned bits[8];
    #pragma unroll
    for (int q = 0; q < 8; q++) {
        float4 sj = s_sh[q * 32 + l];
        float dx = sv.x - sj.x, dy = sv.y - sj.y, dz = sv.z - sj.z, dw = sv.w - sj.w;
        d2[q] = dx * dx + dy * dy + dz * dz + dw * dw;
        bits[q] = __float_as_uint(d2[q]);
    }
    unsigned lo = 0u, hi = 0xFFFFFFFFu;
    #pragma unroll 1
    for (int it = 0; it < 32; it++) {
        unsigned mid = lo + ((hi - lo) >> 1);
        int c = 0;
        #pragma unroll
        for (int q = 0; q < 8; q++) c += (bits[q] <= mid);
        c = __reduce_add_sync(0xFFFFFFFFu, c);
        if (c >= KNB) hi = mid; else lo = mid + 1u;
    }
    unsigned thr = lo;
    int cl = 0;
    #pragma unroll
    for (int q = 0; q < 8; q++) cl += (bits[q] < thr);
    cl = __reduce_add_sync(0xFFFFFFFFu, cl);
    int need = KNB - cl;
    int jlo = 0, jhi = VV - 1;
    #pragma unroll 1
    for (int it = 0; it < 8; it++) {
        int jm = (jlo + jhi) >> 1;
        int c = 0;
        #pragma unroll
        for (int q = 0; q < 8; q++) c += (bits[q] == thr && (q * 32 + l) <= jm);
        c = __reduce_add_sync(0xFFFFFFFFu, c);
        if (c >= need) jhi = jm; else jlo = jm + 1;
    }
    int jthr = jlo;

    int row = b * VV + i;
    int base = 0;
    #pragma unroll
    for (int q = 0; q < 8; q++) {
        int j = q * 32 + l;
        bool sel = (bits[q] < thr) || (bits[q] == thr && j <= jthr);
        unsigned bal = __ballot_sync(0xFFFFFFFFu, sel);
        if (sel) {
            int pos = base + __popc(bal & ((1u << l) - 1u));
            g_nidx[row * KNB + pos] = j;
            g_nw  [row * KNB + pos] = __expf(-10.0f * d2[q]);
        }
        base += __popc(bal);
    }
}

// ============ K_AGG: weighted mean/max gather, block per batch ===============
#define LRP 68
#define SIP 257
#define KA_SMEM ((VV * LRP + 2 * KNB * SIP) * 4)
__global__ void k_agg() {
    extern __shared__ float sh[];
    float* lr_sh = sh;                       // [256][68]
    float* sw    = sh + VV * LRP;            // [40][257]
    int*   sidx  = (int*)(sw + KNB * SIP);   // [40][257]
    int b = blockIdx.x;
    int i = threadIdx.x;

    const float* lrg = g_lr + (size_t)b * VV * NLR;
    for (int e = i; e < VV * NLR; e += VV) {
        int r = e >> 6, c = e & 63;
        lr_sh[r * LRP + c] = lrg[e];
    }
    const int*   gi = g_nidx + (size_t)b * VV * KNB;
    const float* gw = g_nw   + (size_t)b * VV * KNB;
    for (int e = i; e < VV * KNB; e += VV) {
        int r = e / KNB, k = e - r * KNB;
        sidx[k * SIP + r] = gi[e];
        sw  [k * SIP + r] = gw[e];
    }
    __syncthreads();

    float* om = g_mean + ((size_t)b * VV + i) * NLR;
    float* ox = g_max  + ((size_t)b * VV + i) * NLR;
    #pragma unroll
    for (int c0 = 0; c0 < NLR; c0 += 16) {
        float m[16], mx[16];
        #pragma unroll
        for (int f = 0; f < 16; f++) { m[f] = 0.f; mx[f] = 0.f; }
        for (int k = 0; k < KNB; k++) {
            int   j = sidx[k * SIP + i];
            float w = sw  [k * SIP + i];
            const float4* rowp = (const float4*)&lr_sh[j * LRP + c0];
            #pragma unroll
            for (int qq = 0; qq < 4; qq++) {
                float4 lv = rowp[qq];
                float v0 = lv.x * w, v1 = lv.y * w, v2 = lv.z * w, v3 = lv.w * w;
                m [qq*4+0] += v0; m [qq*4+1] += v1; m [qq*4+2] += v2; m [qq*4+3] += v3;
                mx[qq*4+0] = fmaxf(mx[qq*4+0], v0);
                mx[qq*4+1] = fmaxf(mx[qq*4+1], v1);
                mx[qq*4+2] = fmaxf(mx[qq*4+2], v2);
                mx[qq*4+3] = fmaxf(mx[qq*4+3], v3);
            }
        }
        #pragma unroll
        for (int f = 0; f < 16; f++) {
            om[c0 + f] = m[f] * (1.0f / KNB);
            ox[c0 + f] = mx[f];
        }
    }
}

// ============ K_OUT: out = relu(fp @ W + bb), fma.f32x2, conflict-free LDS ===
// 64 rows x 128 cols per block, 256 threads. bb (bias + mx-block) computed in
// prologue from global W (L2-resident).
#define KOUT 192
#define FPP  193
#define KO_SMEM ((64 * FPP + KOUT * NOUT + NOUT + 64) * 4)
__global__ void k_out(const float* __restrict__ x,
                      const float* __restrict__ W,
                      const float* __restrict__ bias,
                      float* __restrict__ out) {
    extern __shared__ float sh[];
    float* fps = sh;                    // [64][193]
    float* Ws  = fps + 64 * FPP;        // [192][128]
    float* bbs = Ws + KOUT * NOUT;      // [128]
    float* mxs = bbs + NOUT;            // [64]
    int t   = threadIdx.x;
    int bv0 = blockIdx.x * 64;
    int b   = bv0 >> 8;

    if (t < 64) mxs[t] = g_mx[b * FF + t];
    for (int e = t; e < 64 * KOUT; e += 256) {
        int row = e / KOUT, c = e - row * KOUT;
        int bv  = bv0 + row;
        float v;
        if      (c < 64)  v = x     [(size_t)bv * FF  + c];
        else if (c < 128) v = g_mean[(size_t)bv * NLR + (c - 64)];
        else              v = g_max [(size_t)bv * NLR + (c - 128)];
        fps[row * FPP + c] = v;
    }
    for (int e = t; e < KOUT * NOUT; e += 256) {
        int k = e >> 7;
        int src = (k < 64) ? k : (k + 64);      // skip mx block (folded into bb)
        Ws[e] = W[src * NOUT + (e & 127)];
    }
    __syncthreads();

    // bb[c] = bias[c] + sum_k mx[k] * W[(64+k)*128 + c]   (coalesced L2 reads)
    if (t < NOUT) {
        float acc = bias[t];
        const float* wr = W + 64 * NOUT + t;
        #pragma unroll 16
        for (int k = 0; k < 64; k++) acc += mxs[k] * wr[k * NOUT];
        bbs[t] = acc;
    }
    __syncthreads();

    int rg = t >> 4;   // 16 rowgroups x 4 rows
    int cg = t & 15;   // col pairs: (2cg+32u, 2cg+32u+1), u=0..3
    ull acc[4][4];
    #pragma unroll
    for (int u = 0; u < 4; u++) {
        float2 b2 = *(const float2*)&bbs[2 * cg + 32 * u];
        ull bp = pack2(b2.x, b2.y);
        #pragma unroll
        for (int q = 0; q < 4; q++) acc[q][u] = bp;
    }
    const float* fpr = fps + (rg * 4) * FPP;
    #pragma unroll 2
    for (int k = 0; k < KOUT; k++) {
        float a0 = fpr[k], a1 = fpr[FPP + k], a2 = fpr[2 * FPP + k], a3 = fpr[3 * FPP + k];
        ull p0 = pack2(a0, a0), p1 = pack2(a1, a1);
        ull p2 = pack2(a2, a2), p3 = pack2(a3, a3);
        const float* wr = Ws + k * NOUT + 2 * cg;
        #pragma unroll
        for (int u = 0; u < 4; u++) {
            ull w = *(const ull*)(wr + 32 * u);   // LDS.64, conflict-free
            fma2(acc[0][u], p0, w);
            fma2(acc[1][u], p1, w);
            fma2(acc[2][u], p2, w);
            fma2(acc[3][u], p3, w);
        }
    }
    #pragma unroll
    for (int q = 0; q < 4; q++) {
        float* op = out + (size_t)(bv0 + rg * 4 + q) * NOUT + 2 * cg;
        #pragma unroll
        for (int u = 0; u < 4; u++) {
            float lo, hi; unpack2(acc[q][u], lo, hi);
            float2 o; o.x = fmaxf(lo, 0.f); o.y = fmaxf(hi, 0.f);
            *(float2*)(op + 32 * u) = o;
        }
    }
}

// ---------------- launch ------------------------------------------------------
extern "C" void kernel_launch(void* const* d_in, const int* in_sizes, int n_in,
                              void* d_out, int out_size) {
    const float* x     = (const float*)d_in[0];
    const float* W_slr = (const float*)d_in[1];
    const float* b_slr = (const float*)d_in[2];
    const float* W_out = (const float*)d_in[3];
    const float* b_out = (const float*)d_in[4];
    float* out = (float*)d_out;

    static bool attr_done = false;
    if (!attr_done) {
        cudaFuncSetAttribute(k_front, cudaFuncAttributeMaxDynamicSharedMemorySize, KF_SMEM);
        cudaFuncSetAttribute(k_agg,   cudaFuncAttributeMaxDynamicSharedMemorySize, KA_SMEM);
        cudaFuncSetAttribute(k_out,   cudaFuncAttributeMaxDynamicSharedMemorySize, KO_SMEM);
        attr_done = true;
    }

    k_front<<<BB, 256, KF_SMEM>>>(x, W_slr, b_slr);
    k_sel  <<<BB * VV / 8, 256>>>();
    k_agg  <<<BB, VV, KA_SMEM>>>();
    k_out  <<<BB * VV / 64, 256, KO_SMEM>>>(x, W_out, b_out, out);
}

// round 6
// speedup vs baseline: 1.2258x; 1.2258x over previous
#include <cuda_runtime.h>

#define BB   128
#define VV   256
#define FF   64
#define NS   4
#define NLR  64
#define NSLR 68
#define KNB  40
#define NOUT 128

// ---------------- scratch ----------------------------------------------------
__device__ float g_mx  [BB * FF];
__device__ float g_s   [BB * VV * NS];
__device__ float g_lr  [BB * VV * NLR];
__device__ float g_mean[BB * VV * NLR];
__device__ float g_max [BB * VV * NLR];
__device__ int   g_nidx[BB * VV * KNB];
__device__ float g_nw  [BB * VV * KNB];
__device__ float g_bb  [BB * NOUT];      // b_out + mx @ W_out[64:128]

// ---------------- packed f32x2 helpers ---------------------------------------
typedef unsigned long long ull;
__device__ __forceinline__ ull pack2(float lo, float hi) {
    ull r; asm("mov.b64 %0, {%1, %2};" : "=l"(r) : "f"(lo), "f"(hi)); return r;
}
__device__ __forceinline__ void unpack2(ull v, float& lo, float& hi) {
    asm("mov.b64 {%0, %1}, %2;" : "=f"(lo), "=f"(hi) : "l"(v));
}
__device__ __forceinline__ void fma2(ull& d, ull a, ull b) {
    asm("fma.rn.f32x2 %0, %1, %2, %0;" : "+l"(d) : "l"(a), "l"(b));
}

// ============ K_FRONT: mean + slr GEMM + output-bias precompute ==============
#define XSP 65
#define KF_SMEM ((VV * XSP + 128 * NSLR + 64 + 256 + NSLR) * 4)
__global__ void k_front(const float* __restrict__ x,
                        const float* __restrict__ W,
                        const float* __restrict__ bias,
                        const float* __restrict__ W_out,
                        const float* __restrict__ b_out) {
    extern __shared__ float sh[];
    float* xs   = sh;                       // [256][65]
    float* Wsh  = xs + VV * XSP;            // [128][68]
    float* mean = Wsh + 128 * NSLR;         // [64]
    float* red  = mean + 64;                // [256]
    float* cc   = red + 256;                // [68]
    int b = blockIdx.x;
    int t = threadIdx.x;

    const float* xb = x + (size_t)b * VV * FF;
    for (int e = t; e < VV * FF; e += 256) {
        int row = e >> 6, c = e & 63;
        xs[row * XSP + c] = xb[e];
    }
    for (int e = t; e < 128 * NSLR; e += 256) Wsh[e] = W[e];
    __syncthreads();

    {
        int f = t & 63, vg = t >> 6;
        float acc = 0.f;
        #pragma unroll 8
        for (int v = vg * 64; v < vg * 64 + 64; v++) acc += xs[v * XSP + f];
        red[vg * 64 + f] = acc;
    }
    __syncthreads();
    if (t < 64) {
        float m = (red[t] + red[64 + t] + red[128 + t] + red[192 + t]) * (1.0f / VV);
        mean[t] = m;
        g_mx[b * FF + t] = m;
    }
    __syncthreads();

    // cc = b_slr + mean-half of slr GEMM
    if (t < NSLR) {
        float acc = bias[t];
        #pragma unroll 8
        for (int k = 0; k < 64; k++) acc += mean[k] * Wsh[(64 + k) * NSLR + t];
        cc[t] = acc;
    }
    // g_bb = b_out + mean-half of output GEMM (was k_bias)
    if (t < NOUT) {
        float acc = b_out[t];
        const float* wr = W_out + 64 * NOUT + t;
        #pragma unroll 16
        for (int k = 0; k < 64; k++) acc += mean[k] * wr[k * NOUT];
        g_bb[b * NOUT + t] = acc;
    }
    __syncthreads();

    int rg = t >> 2;
    int cg = t & 3;
    float acc[4][17];
    #pragma unroll
    for (int u = 0; u < 17; u++) {
        float c0 = cc[cg * 17 + u];
        #pragma unroll
        for (int q = 0; q < 4; q++) acc[q][u] = c0;
    }
    const float* xr = xs + (rg * 4) * XSP;
    #pragma unroll 2
    for (int k = 0; k < 64; k++) {
        float a0 = xr[k], a1 = xr[XSP + k], a2 = xr[2 * XSP + k], a3 = xr[3 * XSP + k];
        const float* wrow = Wsh + k * NSLR + cg * 17;
        #pragma unroll
        for (int u = 0; u < 17; u++) {
            float w = wrow[u];
            acc[0][u] += a0 * w; acc[1][u] += a1 * w;
            acc[2][u] += a2 * w; acc[3][u] += a3 * w;
        }
    }
    #pragma unroll
    for (int q = 0; q < 4; q++) {
        int bv = b * VV + rg * 4 + q;
        #pragma unroll
        for (int u = 0; u < 17; u++) {
            int col = cg * 17 + u;
            float v = fmaxf(acc[q][u], 0.f);
            if (col < NS) g_s [bv * NS  + col]       = v;
            else          g_lr[bv * NLR + col - NS]  = v;
        }
    }
}

// ============ K_SEL: warp-per-row top-40 by (d2, idx) ========================
__global__ void k_sel() {
    __shared__ float4 s_sh[VV];
    int b = blockIdx.x >> 5;
    int i = ((blockIdx.x & 31) << 3) + (threadIdx.x >> 5);
    int l = threadIdx.x & 31;
    if (threadIdx.x < VV)
        s_sh[threadIdx.x] = ((const float4*)g_s)[b * VV + threadIdx.x];
    __syncthreads();

    float4 sv = s_sh[i];
    float d2[8]; unsigned bits[8];
    #pragma unroll
    for (int q = 0; q < 8; q++) {
        float4 sj = s_sh[q * 32 + l];
        float dx = sv.x - sj.x, dy = sv.y - sj.y, dz = sv.z - sj.z, dw = sv.w - sj.w;
        d2[q] = dx * dx + dy * dy + dz * dz + dw * dw;
        bits[q] = __float_as_uint(d2[q]);
    }
    unsigned lo = 0u, hi = 0xFFFFFFFFu;
    #pragma unroll 1
    for (int it = 0; it < 32; it++) {
        unsigned mid = lo + ((hi - lo) >> 1);
        int c = 0;
        #pragma unroll
        for (int q = 0; q < 8; q++) c += (bits[q] <= mid);
        c = __reduce_add_sync(0xFFFFFFFFu, c);
        if (c >= KNB) hi = mid; else lo = mid + 1u;
    }
    unsigned thr = lo;
    int cl = 0;
    #pragma unroll
    for (int q = 0; q < 8; q++) cl += (bits[q] < thr);
    cl = __reduce_add_sync(0xFFFFFFFFu, cl);
    int need = KNB - cl;
    int jlo = 0, jhi = VV - 1;
    #pragma unroll 1
    for (int it = 0; it < 8; it++) {
        int jm = (jlo + jhi) >> 1;
        int c = 0;
        #pragma unroll
        for (int q = 0; q < 8; q++) c += (bits[q] == thr && (q * 32 + l) <= jm);
        c = __reduce_add_sync(0xFFFFFFFFu, c);
        if (c >= need) jhi = jm; else jlo = jm + 1;
    }
    int jthr = jlo;

    int row = b * VV + i;
    int base = 0;
    #pragma unroll
    for (int q = 0; q < 8; q++) {
        int j = q * 32 + l;
        bool sel = (bits[q] < thr) || (bits[q] == thr && j <= jthr);
        unsigned bal = __ballot_sync(0xFFFFFFFFu, sel);
        if (sel) {
            int pos = base + __popc(bal & ((1u << l) - 1u));
            g_nidx[row * KNB + pos] = j;
            g_nw  [row * KNB + pos] = __expf(-10.0f * d2[q]);
        }
        base += __popc(bal);
    }
}

// ============ K_AGG: weighted mean/max gather, block per batch ===============
#define LRP 68
#define SIP 257
#define KA_SMEM ((VV * LRP + 2 * KNB * SIP) * 4)
__global__ void k_agg() {
    extern __shared__ float sh[];
    float* lr_sh = sh;                       // [256][68]
    float* sw    = sh + VV * LRP;            // [40][257]
    int*   sidx  = (int*)(sw + KNB * SIP);   // [40][257]
    int b = blockIdx.x;
    int i = threadIdx.x;

    const float* lrg = g_lr + (size_t)b * VV * NLR;
    for (int e = i; e < VV * NLR; e += VV) {
        int r = e >> 6, c = e & 63;
        lr_sh[r * LRP + c] = lrg[e];
    }
    const int*   gi = g_nidx + (size_t)b * VV * KNB;
    const float* gw = g_nw   + (size_t)b * VV * KNB;
    for (int e = i; e < VV * KNB; e += VV) {
        int r = e / KNB, k = e - r * KNB;
        sidx[k * SIP + r] = gi[e];
        sw  [k * SIP + r] = gw[e];
    }
    __syncthreads();

    float* om = g_mean + ((size_t)b * VV + i) * NLR;
    float* ox = g_max  + ((size_t)b * VV + i) * NLR;
    #pragma unroll
    for (int c0 = 0; c0 < NLR; c0 += 16) {
        float m[16], mx[16];
        #pragma unroll
        for (int f = 0; f < 16; f++) { m[f] = 0.f; mx[f] = 0.f; }
        for (int k = 0; k < KNB; k++) {
            int   j = sidx[k * SIP + i];
            float w = sw  [k * SIP + i];
            const float4* rowp = (const float4*)&lr_sh[j * LRP + c0];
            #pragma unroll
            for (int qq = 0; qq < 4; qq++) {
                float4 lv = rowp[qq];
                float v0 = lv.x * w, v1 = lv.y * w, v2 = lv.z * w, v3 = lv.w * w;
                m [qq*4+0] += v0; m [qq*4+1] += v1; m [qq*4+2] += v2; m [qq*4+3] += v3;
                mx[qq*4+0] = fmaxf(mx[qq*4+0], v0);
                mx[qq*4+1] = fmaxf(mx[qq*4+1], v1);
                mx[qq*4+2] = fmaxf(mx[qq*4+2], v2);
                mx[qq*4+3] = fmaxf(mx[qq*4+3], v3);
            }
        }
        #pragma unroll
        for (int f = 0; f < 16; f++) {
            om[c0 + f] = m[f] * (1.0f / KNB);
            ox[c0 + f] = mx[f];
        }
    }
}

// ============ K_OUT: out = relu(fp @ W + bb) =================================
// 64 rows x 128 cols per block, 256 threads. fp staged TRANSPOSED in smem
// (fpT[k][row], stride 66) -> row-pair LDS.64 feeds fma.f32x2 directly.
// W read from global (L1/L2-resident, 98KB shared by all 512 blocks).
// Thread tile: 8 rows (4 pairs) x 4 cols = 16 fma2 per k.
#define ROWS_O 64
#define FTP    66
#define KOUT   192
#define KO_SMEM ((KOUT * FTP + NOUT) * 4)
__global__ void k_out(const float* __restrict__ x,
                      const float* __restrict__ W,
                      float* __restrict__ out) {
    extern __shared__ float sh[];
    float* fpT = sh;                     // [192][66]
    float* bbs = fpT + KOUT * FTP;       // [128]
    int t   = threadIdx.x;
    int bv0 = blockIdx.x * ROWS_O;
    int b   = bv0 >> 8;

    // stage fp transposed (coalesced global reads, 2-way-conflict smem writes)
    for (int e = t; e < ROWS_O * KOUT; e += 256) {
        int row = e / KOUT, c = e - row * KOUT;
        int bv  = bv0 + row;
        float v;
        if      (c < 64)  v = x     [(size_t)bv * FF  + c];
        else if (c < 128) v = g_mean[(size_t)bv * NLR + (c - 64)];
        else              v = g_max [(size_t)bv * NLR + (c - 128)];
        fpT[c * FTP + row] = v;
    }
    if (t < NOUT) bbs[t] = g_bb[b * NOUT + t];
    __syncthreads();

    int rg = t >> 5;         // 0..7 rowgroup -> rows rg*8 .. rg*8+7
    int cg = t & 31;         // 0..31 colgroup -> cols cg*4 .. cg*4+3

    ull acc[4][4];           // [rowpair][col]
    #pragma unroll
    for (int c = 0; c < 4; c++) {
        float bv = bbs[cg * 4 + c];
        ull bp = pack2(bv, bv);
        #pragma unroll
        for (int rp = 0; rp < 4; rp++) acc[rp][c] = bp;
    }

    const float* fbase = fpT + rg * 8;
    const float4* wp0 = (const float4*)(W) + cg;                 // k in [0,64): row k
    const float4* wp1 = (const float4*)(W + 128 * NOUT) + cg;    // k in [64,192): row k+64

    #pragma unroll 2
    for (int k = 0; k < 64; k++) {
        const float* fk = fbase + k * FTP;
        ull a0 = *(const ull*)(fk);
        ull a1 = *(const ull*)(fk + 2);
        ull a2 = *(const ull*)(fk + 4);
        ull a3 = *(const ull*)(fk + 6);
        float4 w4 = __ldg(wp0 + (size_t)k * 32);
        ull w0 = pack2(w4.x, w4.x), w1 = pack2(w4.y, w4.y);
        ull w2 = pack2(w4.z, w4.z), w3 = pack2(w4.w, w4.w);
        fma2(acc[0][0], a0, w0); fma2(acc[1][0], a1, w0); fma2(acc[2][0], a2, w0); fma2(acc[3][0], a3, w0);
        fma2(acc[0][1], a0, w1); fma2(acc[1][1], a1, w1); fma2(acc[2][1], a2, w1); fma2(acc[3][1], a3, w1);
        fma2(acc[0][2], a0, w2); fma2(acc[1][2], a1, w2); fma2(acc[2][2], a2, w2); fma2(acc[3][2], a3, w2);
        fma2(acc[0][3], a0, w3); fma2(acc[1][3], a1, w3); fma2(acc[2][3], a2, w3); fma2(acc[3][3], a3, w3);
    }
    #pragma unroll 2
    for (int k = 64; k < 192; k++) {
        const float* fk = fbase + k * FTP;
        ull a0 = *(const ull*)(fk);
        ull a1 = *(const ull*)(fk + 2);
        ull a2 = *(const ull*)(fk + 4);
        ull a3 = *(const ull*)(fk + 6);
        float4 w4 = __ldg(wp1 + (size_t)(k - 64) * 32);
        ull w0 = pack2(w4.x, w4.x), w1 = pack2(w4.y, w4.y);
        ull w2 = pack2(w4.z, w4.z), w3 = pack2(w4.w, w4.w);
        fma2(acc[0][0], a0, w0); fma2(acc[1][0], a1, w0); fma2(acc[2][0], a2, w0); fma2(acc[3][0], a3, w0);
        fma2(acc[0][1], a0, w1); fma2(acc[1][1], a1, w1); fma2(acc[2][1], a2, w1); fma2(acc[3][1], a3, w1);
        fma2(acc[0][2], a0, w2); fma2(acc[1][2], a1, w2); fma2(acc[2][2], a2, w2); fma2(acc[3][2], a3, w2);
        fma2(acc[0][3], a0, w3); fma2(acc[1][3], a1, w3); fma2(acc[2][3], a2, w3); fma2(acc[3][3], a3, w3);
    }

    // epilogue: per row, assemble float4 of 4 cols -> coalesced STG.128
    #pragma unroll
    for (int rp = 0; rp < 4; rp++) {
        float lo0, hi0, lo1, hi1, lo2, hi2, lo3, hi3;
        unpack2(acc[rp][0], lo0, hi0);
        unpack2(acc[rp][1], lo1, hi1);
        unpack2(acc[rp][2], lo2, hi2);
        unpack2(acc[rp][3], lo3, hi3);
        float4 o0, o1;
        o0.x = fmaxf(lo0, 0.f); o0.y = fmaxf(lo1, 0.f);
        o0.z = fmaxf(lo2, 0.f); o0.w = fmaxf(lo3, 0.f);
        o1.x = fmaxf(hi0, 0.f); o1.y = fmaxf(hi1, 0.f);
        o1.z = fmaxf(hi2, 0.f); o1.w = fmaxf(hi3, 0.f);
        int r0 = bv0 + rg * 8 + rp * 2;
        *(float4*)(out + (size_t)r0 * NOUT + cg * 4)       = o0;
        *(float4*)(out + (size_t)(r0 + 1) * NOUT + cg * 4) = o1;
    }
}

// ---------------- launch ------------------------------------------------------
extern "C" void kernel_launch(void* const* d_in, const int* in_sizes, int n_in,
                              void* d_out, int out_size) {
    const float* x     = (const float*)d_in[0];
    const float* W_slr = (const float*)d_in[1];
    const float* b_slr = (const float*)d_in[2];
    const float* W_out = (const float*)d_in[3];
    const float* b_out = (const float*)d_in[4];
    float* out = (float*)d_out;

    static bool attr_done = false;
    if (!attr_done) {
        cudaFuncSetAttribute(k_front, cudaFuncAttributeMaxDynamicSharedMemorySize, KF_SMEM);
        cudaFuncSetAttribute(k_agg,   cudaFuncAttributeMaxDynamicSharedMemorySize, KA_SMEM);
        cudaFuncSetAttribute(k_out,   cudaFuncAttributeMaxDynamicSharedMemorySize, KO_SMEM);
        attr_done = true;
    }

    k_front<<<BB, 256, KF_SMEM>>>(x, W_slr, b_slr, W_out, b_out);
    k_sel  <<<BB * VV / 8, 256>>>();
    k_agg  <<<BB, VV, KA_SMEM>>>();
    k_out  <<<BB * VV / ROWS_O, 256, KO_SMEM>>>(x, W_out, out);
}

// round 7
// speedup vs baseline: 1.5060x; 1.2286x over previous
#include <cuda_runtime.h>

#define BB   128
#define VV   256
#define FF   64
#define NS   4
#define NLR  64
#define NSLR 68
#define KNB  40
#define NOUT 128
#define KOUT 192

// ---------------- scratch ----------------------------------------------------
__device__ float g_mx  [BB * FF];
__device__ float g_s   [BB * VV * NS];
__device__ float g_lr  [BB * VV * NLR];
__device__ int   g_nidx[BB * VV * KNB];
__device__ float g_nw  [BB * VV * KNB];
__device__ float g_bb  [BB * NOUT];               // b_out + mx @ W_out[64:128]
__device__ float g_fpT [BB * KOUT * VV];          // transposed fp: [b][k][v]

// ---------------- packed f32x2 helpers ---------------------------------------
typedef unsigned long long ull;
__device__ __forceinline__ ull pack2(float lo, float hi) {
    ull r; asm("mov.b64 %0, {%1, %2};" : "=l"(r) : "f"(lo), "f"(hi)); return r;
}
__device__ __forceinline__ void unpack2(ull v, float& lo, float& hi) {
    asm("mov.b64 {%0, %1}, %2;" : "=f"(lo), "=f"(hi) : "l"(v));
}
__device__ __forceinline__ void fma2(ull& d, ull a, ull b) {
    asm("fma.rn.f32x2 %0, %1, %2, %0;" : "+l"(d) : "l"(a), "l"(b));
}

// ============ K_FRONT: mean + slr GEMM + out-bias + x-transpose ==============
#define XSP 65
#define KF_SMEM ((VV * XSP + 128 * NSLR + 64 + 256 + NSLR) * 4)
__global__ void k_front(const float* __restrict__ x,
                        const float* __restrict__ W,
                        const float* __restrict__ bias,
                        const float* __restrict__ W_out,
                        const float* __restrict__ b_out) {
    extern __shared__ float sh[];
    float* xs   = sh;                       // [256][65]
    float* Wsh  = xs + VV * XSP;            // [128][68]
    float* mean = Wsh + 128 * NSLR;         // [64]
    float* red  = mean + 64;                // [256]
    float* cc   = red + 256;                // [68]
    int b = blockIdx.x;
    int t = threadIdx.x;

    const float* xb = x + (size_t)b * VV * FF;
    for (int e = t; e < VV * FF; e += 256) {
        int row = e >> 6, c = e & 63;
        xs[row * XSP + c] = xb[e];
    }
    for (int e = t; e < 128 * NSLR; e += 256) Wsh[e] = W[e];
    __syncthreads();

    // x-part of transposed fp: g_fpT[b][k][v] = x[b][v][k], k<64
    {
        float* dst = g_fpT + (size_t)b * KOUT * VV;
        for (int e = t; e < FF * VV; e += 256) {
            int k = e >> 8, v = e & 255;
            dst[e] = xs[v * XSP + k];
        }
    }

    {
        int f = t & 63, vg = t >> 6;
        float acc = 0.f;
        #pragma unroll 8
        for (int v = vg * 64; v < vg * 64 + 64; v++) acc += xs[v * XSP + f];
        red[vg * 64 + f] = acc;
    }
    __syncthreads();
    if (t < 64) {
        float m = (red[t] + red[64 + t] + red[128 + t] + red[192 + t]) * (1.0f / VV);
        mean[t] = m;
        g_mx[b * FF + t] = m;
    }
    __syncthreads();

    if (t < NSLR) {
        float acc = bias[t];
        #pragma unroll 8
        for (int k = 0; k < 64; k++) acc += mean[k] * Wsh[(64 + k) * NSLR + t];
        cc[t] = acc;
    }
    if (t < NOUT) {
        float acc = b_out[t];
        const float* wr = W_out + 64 * NOUT + t;
        #pragma unroll 16
        for (int k = 0; k < 64; k++) acc += mean[k] * wr[k * NOUT];
        g_bb[b * NOUT + t] = acc;
    }
    __syncthreads();

    int rg = t >> 2;
    int cg = t & 3;
    float acc[4][17];
    #pragma unroll
    for (int u = 0; u < 17; u++) {
        float c0 = cc[cg * 17 + u];
        #pragma unroll
        for (int q = 0; q < 4; q++) acc[q][u] = c0;
    }
    const float* xr = xs + (rg * 4) * XSP;
    #pragma unroll 2
    for (int k = 0; k < 64; k++) {
        float a0 = xr[k], a1 = xr[XSP + k], a2 = xr[2 * XSP + k], a3 = xr[3 * XSP + k];
        const float* wrow = Wsh + k * NSLR + cg * 17;
        #pragma unroll
        for (int u = 0; u < 17; u++) {
            float w = wrow[u];
            acc[0][u] += a0 * w; acc[1][u] += a1 * w;
            acc[2][u] += a2 * w; acc[3][u] += a3 * w;
        }
    }
    #pragma unroll
    for (int q = 0; q < 4; q++) {
        int bv = b * VV + rg * 4 + q;
        #pragma unroll
        for (int u = 0; u < 17; u++) {
            int col = cg * 17 + u;
            float v = fmaxf(acc[q][u], 0.f);
            if (col < NS) g_s [bv * NS  + col]       = v;
            else          g_lr[bv * NLR + col - NS]  = v;
        }
    }
}

// ============ K_SEL: warp-per-row top-40 by (d2, idx) ========================
__global__ void k_sel() {
    __shared__ float4 s_sh[VV];
    int b = blockIdx.x >> 5;
    int i = ((blockIdx.x & 31) << 3) + (threadIdx.x >> 5);
    int l = threadIdx.x & 31;
    if (threadIdx.x < VV)
        s_sh[threadIdx.x] = ((const float4*)g_s)[b * VV + threadIdx.x];
    __syncthreads();

    float4 sv = s_sh[i];
    float d2[8]; unsigned bits[8];
    #pragma unroll
    for (int q = 0; q < 8; q++) {
        float4 sj = s_sh[q * 32 + l];
        float dx = sv.x - sj.x, dy = sv.y - sj.y, dz = sv.z - sj.z, dw = sv.w - sj.w;
        d2[q] = dx * dx + dy * dy + dz * dz + dw * dw;
        bits[q] = __float_as_uint(d2[q]);
    }
    unsigned lo = 0u, hi = 0xFFFFFFFFu;
    #pragma unroll 1
    for (int it = 0; it < 32; it++) {
        unsigned mid = lo + ((hi - lo) >> 1);
        int c = 0;
        #pragma unroll
        for (int q = 0; q < 8; q++) c += (bits[q] <= mid);
        c = __reduce_add_sync(0xFFFFFFFFu, c);
        if (c >= KNB) hi = mid; else lo = mid + 1u;
    }
    unsigned thr = lo;
    int cl = 0;
    #pragma unroll
    for (int q = 0; q < 8; q++) cl += (bits[q] < thr);
    cl = __reduce_add_sync(0xFFFFFFFFu, cl);
    int need = KNB - cl;
    int jlo = 0, jhi = VV - 1;
    #pragma unroll 1
    for (int it = 0; it < 8; it++) {
        int jm = (jlo + jhi) >> 1;
        int c = 0;
        #pragma unroll
        for (int q = 0; q < 8; q++) c += (bits[q] == thr && (q * 32 + l) <= jm);
        c = __reduce_add_sync(0xFFFFFFFFu, c);
        if (c >= need) jhi = jm; else jlo = jm + 1;
    }
    int jthr = jlo;

    int row = b * VV + i;
    int base = 0;
    #pragma unroll
    for (int q = 0; q < 8; q++) {
        int j = q * 32 + l;
        bool sel = (bits[q] < thr) || (bits[q] == thr && j <= jthr);
        unsigned bal = __ballot_sync(0xFFFFFFFFu, sel);
        if (sel) {
            int pos = base + __popc(bal & ((1u << l) - 1u));
            g_nidx[row * KNB + pos] = j;
            g_nw  [row * KNB + pos] = __expf(-10.0f * d2[q]);
        }
        base += __popc(bal);
    }
}

// ============ K_AGG: weighted mean/max gather -> transposed fpT ==============
#define LRP 68
#define SIP 257
#define KA_SMEM ((VV * LRP + 2 * KNB * SIP) * 4)
__global__ void k_agg() {
    extern __shared__ float sh[];
    float* lr_sh = sh;                       // [256][68]
    float* sw    = sh + VV * LRP;            // [40][257]
    int*   sidx  = (int*)(sw + KNB * SIP);   // [40][257]
    int b = blockIdx.x;
    int i = threadIdx.x;

    const float* lrg = g_lr + (size_t)b * VV * NLR;
    for (int e = i; e < VV * NLR; e += VV) {
        int r = e >> 6, c = e & 63;
        lr_sh[r * LRP + c] = lrg[e];
    }
    const int*   gi = g_nidx + (size_t)b * VV * KNB;
    const float* gw = g_nw   + (size_t)b * VV * KNB;
    for (int e = i; e < VV * KNB; e += VV) {
        int r = e / KNB, k = e - r * KNB;
        sidx[k * SIP + r] = gi[e];
        sw  [k * SIP + r] = gw[e];
    }
    __syncthreads();

    // dst[c*256 + i]: lanes i consecutive -> coalesced stores per feature c
    float* dm = g_fpT + (size_t)b * KOUT * VV + (size_t)64  * VV + i;
    float* dx = g_fpT + (size_t)b * KOUT * VV + (size_t)128 * VV + i;
    #pragma unroll
    for (int c0 = 0; c0 < NLR; c0 += 16) {
        float m[16], mx[16];
        #pragma unroll
        for (int f = 0; f < 16; f++) { m[f] = 0.f; mx[f] = 0.f; }
        for (int k = 0; k < KNB; k++) {
            int   j = sidx[k * SIP + i];
            float w = sw  [k * SIP + i];
            const float4* rowp = (const float4*)&lr_sh[j * LRP + c0];
            #pragma unroll
            for (int qq = 0; qq < 4; qq++) {
                float4 lv = rowp[qq];
                float v0 = lv.x * w, v1 = lv.y * w, v2 = lv.z * w, v3 = lv.w * w;
                m [qq*4+0] += v0; m [qq*4+1] += v1; m [qq*4+2] += v2; m [qq*4+3] += v3;
                mx[qq*4+0] = fmaxf(mx[qq*4+0], v0);
                mx[qq*4+1] = fmaxf(mx[qq*4+1], v1);
                mx[qq*4+2] = fmaxf(mx[qq*4+2], v2);
                mx[qq*4+3] = fmaxf(mx[qq*4+3], v3);
            }
        }
        #pragma unroll
        for (int f = 0; f < 16; f++) {
            dm[(c0 + f) * VV] = m[f] * (1.0f / KNB);
            dx[(c0 + f) * VV] = mx[f];
        }
    }
}

// ============ K_OUT: out = relu(fpT^T @ W + bb) ==============================
// 32 rows x 128 cols per block, 1024 blocks, 256 threads.
// fs[k][row] staged by straight coalesced copy (no div/transpose).
// Thread tile: 4 rows (2 f32x2 pairs) x 4 cols = 8 fma2 per k.
#define ROWS_O 32
#define KO_SMEM ((KOUT * ROWS_O + NOUT) * 4)
__global__ void k_out(const float* __restrict__ W,
                      float* __restrict__ out) {
    extern __shared__ float sh[];
    float* fs  = sh;                     // [192][32]
    float* bbs = fs + KOUT * ROWS_O;     // [128]
    int t   = threadIdx.x;
    int bv0 = blockIdx.x * ROWS_O;
    int b   = bv0 >> 8;

    // stage A slice: g_fpT[b][k][bv0 & 255 .. +31]
    const float* src = g_fpT + (size_t)b * KOUT * VV + (bv0 & 255);
    #pragma unroll 6
    for (int e = t; e < KOUT * ROWS_O; e += 256) {
        int k = e >> 5, r = e & 31;
        fs[e] = src[k * VV + r];
    }
    if (t < NOUT) bbs[t] = g_bb[b * NOUT + t];
    __syncthreads();

    int rg = t >> 5;     // 8 rowgroups x 4 rows
    int cg = t & 31;     // 32 colgroups x 4 cols

    ull acc[2][4];       // [rowpair][col]
    #pragma unroll
    for (int c = 0; c < 4; c++) {
        float bv = bbs[cg * 4 + c];
        ull bp = pack2(bv, bv);
        acc[0][c] = bp; acc[1][c] = bp;
    }

    const float*  fb = fs + rg * 4;
    const float4* wp = (const float4*)(W) + cg;   // logical k row via skip below

    #pragma unroll 4
    for (int k = 0; k < KOUT; k++) {
        int ksrc = (k < 64) ? k : (k + 64);       // skip mx block (folded in bb)
        ull a0 = *(const ull*)(fb + k * ROWS_O);
        ull a1 = *(const ull*)(fb + k * ROWS_O + 2);
        float4 w4 = __ldg(wp + (size_t)ksrc * 32);
        ull w0 = pack2(w4.x, w4.x), w1 = pack2(w4.y, w4.y);
        ull w2 = pack2(w4.z, w4.z), w3 = pack2(w4.w, w4.w);
        fma2(acc[0][0], a0, w0); fma2(acc[1][0], a1, w0);
        fma2(acc[0][1], a0, w1); fma2(acc[1][1], a1, w1);
        fma2(acc[0][2], a0, w2); fma2(acc[1][2], a1, w2);
        fma2(acc[0][3], a0, w3); fma2(acc[1][3], a1, w3);
    }

    #pragma unroll
    for (int rp = 0; rp < 2; rp++) {
        float lo0, hi0, lo1, hi1, lo2, hi2, lo3, hi3;
        unpack2(acc[rp][0], lo0, hi0);
        unpack2(acc[rp][1], lo1, hi1);
        unpack2(acc[rp][2], lo2, hi2);
        unpack2(acc[rp][3], lo3, hi3);
        float4 o0, o1;
        o0.x = fmaxf(lo0, 0.f); o0.y = fmaxf(lo1, 0.f);
        o0.z = fmaxf(lo2, 0.f); o0.w = fmaxf(lo3, 0.f);
        o1.x = fmaxf(hi0, 0.f); o1.y = fmaxf(hi1, 0.f);
        o1.z = fmaxf(hi2, 0.f); o1.w = fmaxf(hi3, 0.f);
        int r0 = bv0 + rg * 4 + rp * 2;
        *(float4*)(out + (size_t)r0 * NOUT + cg * 4)       = o0;
        *(float4*)(out + (size_t)(r0 + 1) * NOUT + cg * 4) = o1;
    }
}

// ---------------- launch ------------------------------------------------------
extern "C" void kernel_launch(void* const* d_in, const int* in_sizes, int n_in,
                              void* d_out, int out_size) {
    const float* x     = (const float*)d_in[0];
    const float* W_slr = (const float*)d_in[1];
    const float* b_slr = (const float*)d_in[2];
    const float* W_out = (const float*)d_in[3];
    const float* b_out = (const float*)d_in[4];
    float* out = (float*)d_out;

    static bool attr_done = false;
    if (!attr_done) {
        cudaFuncSetAttribute(k_front, cudaFuncAttributeMaxDynamicSharedMemorySize, KF_SMEM);
        cudaFuncSetAttribute(k_agg,   cudaFuncAttributeMaxDynamicSharedMemorySize, KA_SMEM);
        cudaFuncSetAttribute(k_out,   cudaFuncAttributeMaxDynamicSharedMemorySize, KO_SMEM);
        attr_done = true;
    }

    k_front<<<BB, 256, KF_SMEM>>>(x, W_slr, b_slr, W_out, b_out);
    k_sel  <<<BB * VV / 8, 256>>>();
    k_agg  <<<BB, VV, KA_SMEM>>>();
    k_out  <<<BB * VV / ROWS_O, 256, KO_SMEM>>>(W_out, out);
}